// round 6
// baseline (speedup 1.0000x reference)
#include <cuda_runtime.h>
#include <cuda_fp16.h>
#include <cstdint>

// ---------------------------------------------------------------------------
// x_{k+1}[v] = relu( sum_d W[v,d]*x_k[src[v,d]] - demand[v] ), 32 iters,
// out = weights * x_32.  B=4, N=100K, D=16 (12 valid).
//
// R6: two-half bulk-copy staging with bidirectional sorted edge packing:
// lower-half edges at rows 0..c0-1 (ascending), upper-half edges at rows
// 15..16-c1 (descending). Phase p waits only on its half's mbarrier =>
// x-broadcast overlaps the edge walk. All lanes at trip i read the same row
// => edge LDG stays coalesced with per-lane trip counts; padding never read.
// ---------------------------------------------------------------------------

#define MAXN       430000
#define MAXSLOT    16
#define TPB        1024
#define DPT        4
#define SMEM_BYTES 200704      // dyn smem for staged fp16 x (N*2 <= this)

__device__ float g_w[(size_t)MAXN * MAXSLOT];   // softmax weights [dst][slot]
__device__ int2  g_e[(size_t)MAXSLOT * MAXN];   // edges SoA [row][dst]: .x=smem byte off, .y=w bits
__device__ int   g_c01[MAXN];                   // c0 | (c1<<16) per dst
__device__ __align__(16) __half g_xa[MAXN];
__device__ __align__(16) __half g_xb[MAXN];

__device__ __forceinline__ unsigned smem_u32(const void* p) {
    unsigned r;
    asm("{ .reg .u64 t; cvta.to.shared.u64 t, %1; cvt.u32.u64 %0, t; }"
        : "=r"(r) : "l"(p));
    return r;
}

__device__ __forceinline__ void mbar_wait(unsigned mb, unsigned parity) {
    unsigned done;
    do {
        asm volatile("{ .reg .pred p; "
                     "mbarrier.try_wait.parity.acquire.cta.shared::cta.b64 p, [%1], %2, 0x989680; "
                     "selp.b32 %0, 1, 0, p; }"
                     : "=r"(done) : "r"(mb), "r"(parity) : "memory");
    } while (!done);
}

// --- K1: masked softmax over D slots (thread per node) ---------------------
__global__ void k_softmax(const float* __restrict__ fp, const int* __restrict__ adj,
                          const int* __restrict__ num_nodes, int BN, int D) {
    int t = blockIdx.x * blockDim.x + threadIdx.x;
    if (t >= BN) return;
    const int N = __ldg(num_nodes);
    const float* f = fp + (size_t)t * D;
    const int*   a = adj + (size_t)t * D;

    float m = -3.402823466e38f;
    for (int d = 0; d < D; ++d) {
        float v = __ldg(f + d);
        if (__ldg(a + d) == N) v -= 1e7f;
        m = fmaxf(m, v);
    }
    float s = 0.f;
    for (int d = 0; d < D; ++d) {
        float v = __ldg(f + d);
        if (__ldg(a + d) == N) v -= 1e7f;
        s += __expf(v - m);
    }
    float inv = 1.f / s;
    for (int d = 0; d < D; ++d) {
        float v = __ldg(f + d);
        if (__ldg(a + d) == N) v -= 1e7f;
        g_w[(size_t)t * D + d] = __expf(v - m) * inv;
    }
}

// --- K2: build bidirectionally-packed sorted edge lists --------------------
// Edge record: .x = intra-batch smem BYTE offset (fs*2), .y = f32 bits of w.
// Sort valid edges by offset; offsets < HB0 go ascending at rows 0..c0-1,
// offsets >= HB0 go at rows (MAXSLOT-1) downward. Middle rows are untouched
// garbage (never read: walk bounds are c0/c1).
__global__ void k_gather(const int* __restrict__ ii, const int* __restrict__ num_nodes,
                         int BN, int D) {
    int t = blockIdx.x * blockDim.x + threadIdx.x;
    if (t >= BN) return;
    const int N = __ldg(num_nodes);
    const int h0  = ((N / 2) + 7) & ~7;        // lower-half node count (16B-aligned bytes)
    const unsigned HB0 = (unsigned)h0 * 2u;    // byte boundary in staged x

    int   soff[MAXSLOT];
    float sw[MAXSLOT];
    int m = 0;
    for (int s = 0; s < D; ++s) {
        const int* r = ii + ((size_t)t * D + s) * 3;
        int fb = __ldg(r + 0);
        int fs = __ldg(r + 1);
        int fl = __ldg(r + 2);
        float w = g_w[((size_t)fb * N + fs) * D + fl];
        if (w != 0.0f) {
            int off = fs * 2;
            int j = m++;
            while (j > 0 && soff[j - 1] > off) {
                soff[j] = soff[j - 1]; sw[j] = sw[j - 1]; --j;
            }
            soff[j] = off; sw[j] = w;
        }
    }
    int c0 = 0;
    while (c0 < m && (unsigned)soff[c0] < HB0) ++c0;
    int c1 = m - c0;
    // lower half: rows 0..c0-1 ascending
    for (int j = 0; j < c0; ++j)
        g_e[(size_t)j * BN + t] = make_int2(soff[j], __float_as_int(sw[j]));
    // upper half: j-th upper edge at row MAXSLOT-1-j
    for (int j = 0; j < c1; ++j)
        g_e[(size_t)(MAXSLOT - 1 - j) * BN + t] =
            make_int2(soff[c0 + j], __float_as_int(sw[c0 + j]));
    g_c01[t] = c0 | (c1 << 16);
}

// --- K3: one iteration; out!=nullptr on last iteration => fused epilogue ---
__global__ void __launch_bounds__(TPB, 1) k_iter6(const float* __restrict__ dem,
                                                  const __half* __restrict__ xo,
                                                  __half* __restrict__ xn,
                                                  float* __restrict__ out,
                                                  int BN, int D,
                                                  const int* __restrict__ num_nodes) {
    extern __shared__ unsigned char xs[];          // N fp16 values (staged x)
    __shared__ __align__(8) unsigned long long mbar0, mbar1;

    const int N   = __ldg(num_nodes);
    const int B   = BN / N;
    const int bpb = gridDim.x / B;
    const int blk = blockIdx.x;
    if (blk >= bpb * B) return;                    // whole-block exit (pre-sync)
    const int b     = blk / bpb;
    const int ib    = blk - b * bpb;
    const int spb   = (N + bpb - 1) / bpb;
    const int start = b * N + ib * spb;
    const int stop  = min(start + spb, (b + 1) * N);

    const int h0  = ((N / 2) + 7) & ~7;
    const unsigned HB0   = (unsigned)h0 * 2u;
    const unsigned bytes = (unsigned)N * 2u;
    const bool whole   = (bytes <= SMEM_BYTES);
    const bool bulk_ok = whole && ((bytes & 15u) == 0u) && (h0 < N);

    const unsigned mb0 = smem_u32(&mbar0);
    const unsigned mb1 = smem_u32(&mbar1);
    if (bulk_ok) {
        if (threadIdx.x == 0) {
            asm volatile("mbarrier.init.shared.b64 [%0], %1;" :: "r"(mb0), "r"(1) : "memory");
            asm volatile("mbarrier.init.shared.b64 [%0], %1;" :: "r"(mb1), "r"(1) : "memory");
        }
        __syncthreads();
        if (threadIdx.x == 0) {
            const unsigned sz0 = HB0, sz1 = bytes - HB0;
            asm volatile("mbarrier.arrive.expect_tx.shared.b64 _, [%0], %1;"
                         :: "r"(mb0), "r"(sz0) : "memory");
            asm volatile("cp.async.bulk.shared::cta.global.mbarrier::complete_tx::bytes "
                         "[%0], [%1], %2, [%3];"
                         :: "r"(smem_u32(xs)), "l"(xo + (size_t)b * N), "r"(sz0), "r"(mb0)
                         : "memory");
            asm volatile("mbarrier.arrive.expect_tx.shared.b64 _, [%0], %1;"
                         :: "r"(mb1), "r"(sz1) : "memory");
            asm volatile("cp.async.bulk.shared::cta.global.mbarrier::complete_tx::bytes "
                         "[%0], [%1], %2, [%3];"
                         :: "r"(smem_u32(xs) + HB0), "l"(xo + (size_t)b * N + h0),
                            "r"(sz1), "r"(mb1)
                         : "memory");
        }
    }

    // prefetch per-dst metadata while copies are in flight
    float dm[DPT];
    int   c0[DPT], c1[DPT];
    int   dl[DPT];
    int   kmax = 0;
#pragma unroll
    for (int k = 0; k < DPT; ++k) {
        int d = start + threadIdx.x + k * TPB;
        bool act = (d < stop);
        dl[k] = min(d, stop - 1);
        dm[k] = act ? __ldg(dem + d) : 0.f;
        int cc = act ? g_c01[d] : 0;
        c0[k] = cc & 0xffff;
        c1[k] = cc >> 16;
        if (start + k * TPB < stop) kmax = k + 1;
    }

    float r_out[DPT];
#pragma unroll
    for (int k = 0; k < DPT; ++k) r_out[k] = 0.f;

    if (whole) {
        if (!bulk_ok) {
            __half* dh = (__half*)xs;
            for (int i = threadIdx.x; i < N; i += TPB)
                dh[i] = __ldg(xo + (size_t)b * N + i);
            __syncthreads();
        } else {
            mbar_wait(mb0, 0u);                    // per-thread acquire: half 0 ready
        }

        // ---- phase 0: lower-half edges, rows 0..c0-1 (lockstep rows) -------
#pragma unroll
        for (int k = 0; k < DPT; ++k) {
            if (k >= kmax) break;
            const int2* ep = g_e + dl[k];
            const int c = c0[k];
            float a = 0.f;
#pragma unroll 4
            for (int pos = 0; pos < c; ++pos) {
                int2 e = ep[pos * BN];
                a = fmaf(__half2float(*(const __half*)(xs + e.x)), __int_as_float(e.y), a);
            }
            r_out[k] = a;
        }

        if (bulk_ok) mbar_wait(mb1, 0u);           // half 1 ready

        // ---- phase 1: upper-half edges, rows 15,14,... (lockstep rows) -----
#pragma unroll
        for (int k = 0; k < DPT; ++k) {
            if (k >= kmax) break;
            const int2* ep = g_e + dl[k];
            const int c = c1[k];
            float a = r_out[k];
#pragma unroll 4
            for (int j = 0; j < c; ++j) {
                int2 e = ep[(MAXSLOT - 1 - j) * BN];
                a = fmaf(__half2float(*(const __half*)(xs + e.x)), __int_as_float(e.y), a);
            }
            r_out[k] = fmaxf(a - dm[k], 0.f);
        }
    } else {
        // ---- generic chunked fallback (N*2 > smem): range-predicated -------
        const int hpc = SMEM_BYTES / 2;
        const int cb  = (N + hpc - 1) / hpc;
        float acc[DPT];
#pragma unroll
        for (int k = 0; k < DPT; ++k) acc[k] = 0.f;
        for (int j = 0; j < cb; ++j) {
            const int lo  = j * hpc;
            const int lim = min(hpc, N - lo);
            __half* dh = (__half*)xs;
            for (int i = threadIdx.x; i < lim; i += TPB)
                dh[i] = __ldg(xo + (size_t)b * N + lo + i);
            __syncthreads();
            const unsigned base2 = (unsigned)lo * 2u, lim2 = (unsigned)lim * 2u;
#pragma unroll
            for (int k = 0; k < DPT; ++k) {
                if (k >= kmax) break;
                const int2* ep = g_e + dl[k];
                float a = acc[k];
                for (int pos = 0; pos < c0[k]; ++pos) {
                    int2 e = ep[pos * BN];
                    unsigned rel = (unsigned)e.x - base2;
                    if (rel < lim2)
                        a = fmaf(__half2float(*(const __half*)(xs + rel)),
                                 __int_as_float(e.y), a);
                }
                for (int jj = 0; jj < c1[k]; ++jj) {
                    int2 e = ep[(MAXSLOT - 1 - jj) * BN];
                    unsigned rel = (unsigned)e.x - base2;
                    if (rel < lim2)
                        a = fmaf(__half2float(*(const __half*)(xs + rel)),
                                 __int_as_float(e.y), a);
                }
                acc[k] = a;
            }
            __syncthreads();
        }
#pragma unroll
        for (int k = 0; k < DPT; ++k)
            r_out[k] = fmaxf(acc[k] - dm[k], 0.f);
    }

    if (out == nullptr) {
#pragma unroll
        for (int k = 0; k < DPT; ++k) {
            int d = start + threadIdx.x + k * TPB;
            if (d < stop) xn[d] = __float2half_rn(r_out[k]);
        }
    } else {
        // LAST iteration: fused epilogue out[d,:] = g_w[d,:] * r (fp32 r)
        __syncthreads();                         // everyone done reading xs
        float* rs = (float*)xs;
#pragma unroll
        for (int k = 0; k < DPT; ++k) {
            int d = start + threadIdx.x + k * TPB;
            if (d < stop) rs[d - start] = r_out[k];
        }
        __syncthreads();
        const int rows = stop - start;
        if ((D & 3) == 0) {
            const int dq = D >> 2;
            const int total4 = rows * dq;
            const float4* w4 = (const float4*)(g_w + (size_t)start * D);
            float4*       o4 = (float4*)(out + (size_t)start * D);
            for (int i = threadIdx.x; i < total4; i += TPB) {
                float4 w = __ldg(w4 + i);
                float  r = rs[i / dq];
                o4[i] = make_float4(w.x * r, w.y * r, w.z * r, w.w * r);
            }
        } else {
            const int total = rows * D;
            for (int i = threadIdx.x; i < total; i += TPB)
                out[(size_t)start * D + i] = g_w[(size_t)start * D + i] * rs[i / D];
        }
    }
}

extern "C" void kernel_launch(void* const* d_in, const int* in_sizes, int n_in,
                              void* d_out, int out_size) {
    const float* fp  = (const float*)d_in[0];   // flow_proportions [B,N,D]
    const float* dem = (const float*)d_in[1];   // demands [B,N,1]
    const int*   adj = (const int*)d_in[2];     // adj_lst [B,N,D]
    const int*   ii  = (const int*)d_in[3];     // in_indices [B,N,D,3]
    const int*   nn  = (const int*)d_in[4];     // num_nodes scalar (device)

    const int E  = in_sizes[0];                 // B*N*D
    const int BN = in_sizes[1];                 // B*N
    const int D  = E / BN;

    void *pxa, *pxb;
    cudaGetSymbolAddress(&pxa, g_xa);
    cudaGetSymbolAddress(&pxb, g_xb);
    __half* xa = (__half*)pxa;
    __half* xb = (__half*)pxb;

    int sm = 148;
    cudaDeviceGetAttribute(&sm, cudaDevAttrMultiProcessorCount, 0);
    const int grid = sm;                        // 152 on GB300 (divisible by B=4)

    cudaFuncSetAttribute(k_iter6, cudaFuncAttributeMaxDynamicSharedMemorySize,
                         SMEM_BYTES);

    const int BT = 256;
    const int gN = (BN + BT - 1) / BT;

    k_softmax<<<gN, BT>>>(fp, adj, nn, BN, D);
    k_gather<<<gN, BT>>>(ii, nn, BN, D);
    cudaMemsetAsync(xa, 0, (size_t)BN * sizeof(__half), 0);

    for (int i = 0; i < 32; ++i) {
        const __half* xo = (i & 1) ? xb : xa;
        __half*       xn = (i & 1) ? xa : xb;
        float* out = (i == 31) ? (float*)d_out : nullptr;
        k_iter6<<<grid, TPB, SMEM_BYTES>>>(dem, xo, xn, out, BN, D, nn);
    }
}

// round 7
// speedup vs baseline: 1.4546x; 1.4546x over previous
#include <cuda_runtime.h>
#include <cuda_fp16.h>
#include <cstdint>

// ---------------------------------------------------------------------------
// x_{k+1}[v] = relu( sum_d W[v,d]*x_k[src[v,d]] - demand[v] ), 32 iters,
// out = weights * x_32.  B=4, N=100K, D=16 (12 valid).
//
// R7 = R5 skeleton (best: uniform zero-padded walk, single bulk-copy staging,
// fused epilogue) + int4 row-pair edge layout (one LDG.128 per 2 edges) +
// first edge pair hoisted above the mbarrier wait.
// ---------------------------------------------------------------------------

#define MAXN       430000
#define MAXSLOT    16
#define MAXPAIR    (MAXSLOT / 2)
#define TPB        1024
#define DPT        4
#define SMEM_BYTES 200704      // dyn smem for staged fp16 x (N*2 <= this)

__device__ float g_w[(size_t)MAXN * MAXSLOT];    // softmax weights [dst][slot]
__device__ int4  g_e[(size_t)MAXPAIR * MAXN];    // edge pairs SoA [pair][dst]:
                                                 //   {off0, w0bits, off1, w1bits}
__device__ int   g_maxcnt;                       // max valid edges per dst
__device__ __align__(16) __half g_xa[MAXN];
__device__ __align__(16) __half g_xb[MAXN];

__device__ __forceinline__ unsigned smem_u32(const void* p) {
    unsigned r;
    asm("{ .reg .u64 t; cvta.to.shared.u64 t, %1; cvt.u32.u64 %0, t; }"
        : "=r"(r) : "l"(p));
    return r;
}

__device__ __forceinline__ void mbar_wait(unsigned mb, unsigned parity) {
    unsigned done;
    do {
        asm volatile("{ .reg .pred p; "
                     "mbarrier.try_wait.parity.acquire.cta.shared::cta.b64 p, [%1], %2, 0x989680; "
                     "selp.b32 %0, 1, 0, p; }"
                     : "=r"(done) : "r"(mb), "r"(parity) : "memory");
    } while (!done);
}

// --- K1: masked softmax over D slots (thread per node) ---------------------
__global__ void k_softmax(const float* __restrict__ fp, const int* __restrict__ adj,
                          const int* __restrict__ num_nodes, int BN, int D) {
    int t = blockIdx.x * blockDim.x + threadIdx.x;
    if (t >= BN) return;
    const int N = __ldg(num_nodes);
    const float* f = fp + (size_t)t * D;
    const int*   a = adj + (size_t)t * D;

    float m = -3.402823466e38f;
    for (int d = 0; d < D; ++d) {
        float v = __ldg(f + d);
        if (__ldg(a + d) == N) v -= 1e7f;
        m = fmaxf(m, v);
    }
    float s = 0.f;
    for (int d = 0; d < D; ++d) {
        float v = __ldg(f + d);
        if (__ldg(a + d) == N) v -= 1e7f;
        s += __expf(v - m);
    }
    float inv = 1.f / s;
    for (int d = 0; d < D; ++d) {
        float v = __ldg(f + d);
        if (__ldg(a + d) == N) v -= 1e7f;
        g_w[(size_t)t * D + d] = __expf(v - m) * inv;
    }
}

// --- K2: build int4 row-pair edge records -----------------------------------
// Valid (w!=0) edges compacted first; remaining slots padded with (0, 0.0f)
// so a fixed pair walk is always safe (0-weight * xs[0] contributes 0).
__global__ void k_gather(const int* __restrict__ ii, const int* __restrict__ num_nodes,
                         int BN, int D) {
    int t = blockIdx.x * blockDim.x + threadIdx.x;
    if (t >= BN) return;
    const int N = __ldg(num_nodes);

    int   off[MAXSLOT];
    int   wb[MAXSLOT];
    int m = 0;
    for (int s = 0; s < D; ++s) {
        const int* r = ii + ((size_t)t * D + s) * 3;
        int fb = __ldg(r + 0);
        int fs = __ldg(r + 1);
        int fl = __ldg(r + 2);
        float w = g_w[((size_t)fb * N + fs) * D + fl];
        if (w != 0.0f) {
            off[m] = fs * 2;              // intra-batch smem byte offset
            wb[m]  = __float_as_int(w);
            ++m;
        }
    }
    for (int s = m; s < D; ++s) { off[s] = 0; wb[s] = 0; }

    const int P = D / 2;
    for (int p = 0; p < P; ++p)
        g_e[(size_t)p * BN + t] = make_int4(off[2 * p], wb[2 * p],
                                            off[2 * p + 1], wb[2 * p + 1]);
    atomicMax(&g_maxcnt, m);
}

// --- K3: one iteration; out!=nullptr on last iteration => fused epilogue ---
__global__ void __launch_bounds__(TPB, 1) k_iter7(const float* __restrict__ dem,
                                                  const __half* __restrict__ xo,
                                                  __half* __restrict__ xn,
                                                  float* __restrict__ out,
                                                  int BN, int D,
                                                  const int* __restrict__ num_nodes) {
    extern __shared__ unsigned char xs[];          // N fp16 values (staged x)
    __shared__ __align__(8) unsigned long long mbar;

    const int N   = __ldg(num_nodes);
    const int B   = BN / N;
    const int bpb = gridDim.x / B;
    const int blk = blockIdx.x;
    if (blk >= bpb * B) return;                    // whole-block exit (pre-sync)
    const int b     = blk / bpb;
    const int ib    = blk - b * bpb;
    const int spb   = (N + bpb - 1) / bpb;
    const int start = b * N + ib * spb;
    const int stop  = min(start + spb, (b + 1) * N);
    const int P     = (g_maxcnt + 1) >> 1;         // pairs to walk

    const unsigned bytes = (unsigned)N * 2u;
    const bool whole   = (bytes <= SMEM_BYTES);
    const bool bulk_ok = whole && ((bytes & 15u) == 0u);

    const unsigned mb = smem_u32(&mbar);
    if (bulk_ok) {
        if (threadIdx.x == 0)
            asm volatile("mbarrier.init.shared.b64 [%0], %1;" :: "r"(mb), "r"(1) : "memory");
        __syncthreads();
        if (threadIdx.x == 0) {
            asm volatile("mbarrier.arrive.expect_tx.shared.b64 _, [%0], %1;"
                         :: "r"(mb), "r"(bytes) : "memory");
            asm volatile("cp.async.bulk.shared::cta.global.mbarrier::complete_tx::bytes "
                         "[%0], [%1], %2, [%3];"
                         :: "r"(smem_u32(xs)), "l"(xo + (size_t)b * N), "r"(bytes), "r"(mb)
                         : "memory");
        }
    }

    // ---- overlap window: everything x-independent happens here -------------
    float dm[DPT];
    int   dl[DPT];
    int   kmax = 0;
#pragma unroll
    for (int k = 0; k < DPT; ++k) {
        int d = start + threadIdx.x + k * TPB;
        dl[k] = min(d, stop - 1);
        dm[k] = (d < stop) ? __ldg(dem + d) : 0.f;
        if (start + k * TPB < stop) kmax = k + 1;
    }
    int4 e0[DPT];                                  // first edge pair, prefetched
#pragma unroll
    for (int k = 0; k < DPT; ++k) {
        if (k >= kmax) break;
        e0[k] = __ldg(&g_e[dl[k]]);
    }

    float r_out[DPT];
#pragma unroll
    for (int k = 0; k < DPT; ++k) r_out[k] = 0.f;

    if (whole) {
        if (!bulk_ok) {
            __half* dh = (__half*)xs;
            for (int i = threadIdx.x; i < N; i += TPB)
                dh[i] = __ldg(xo + (size_t)b * N + i);
            __syncthreads();
        } else {
            mbar_wait(mb, 0u);                     // per-thread acquire
        }

        // ---- uniform pair walk: P lockstep rows, zero pads free ------------
#pragma unroll
        for (int k = 0; k < DPT; ++k) {
            if (k >= kmax) break;
            const int4* ep = g_e + dl[k];
            float a = 0.f;
            int4 e = e0[k];
#pragma unroll 5
            for (int p = 1; p < P; ++p) {
                int4 f = __ldg(ep + p * BN);
                a = fmaf(__half2float(*(const __half*)(xs + e.x)), __int_as_float(e.y), a);
                a = fmaf(__half2float(*(const __half*)(xs + e.z)), __int_as_float(e.w), a);
                e = f;
            }
            a = fmaf(__half2float(*(const __half*)(xs + e.x)), __int_as_float(e.y), a);
            a = fmaf(__half2float(*(const __half*)(xs + e.z)), __int_as_float(e.w), a);
            r_out[k] = fmaxf(a - dm[k], 0.f);
        }
    } else {
        // ---- generic chunked fallback (N*2 > smem): range-predicated -------
        const int hpc = SMEM_BYTES / 2;
        const int cb  = (N + hpc - 1) / hpc;
        float acc[DPT];
#pragma unroll
        for (int k = 0; k < DPT; ++k) acc[k] = 0.f;
        for (int j = 0; j < cb; ++j) {
            const int lo  = j * hpc;
            const int lim = min(hpc, N - lo);
            __half* dh = (__half*)xs;
            for (int i = threadIdx.x; i < lim; i += TPB)
                dh[i] = __ldg(xo + (size_t)b * N + lo + i);
            __syncthreads();
            const unsigned base2 = (unsigned)lo * 2u, lim2 = (unsigned)lim * 2u;
#pragma unroll
            for (int k = 0; k < DPT; ++k) {
                if (k >= kmax) break;
                const int4* ep = g_e + dl[k];
                float a = acc[k];
                for (int p = 0; p < P; ++p) {
                    int4 e = __ldg(ep + p * BN);
                    unsigned r0 = (unsigned)e.x - base2;
                    unsigned r1 = (unsigned)e.z - base2;
                    if (r0 < lim2)
                        a = fmaf(__half2float(*(const __half*)(xs + r0)),
                                 __int_as_float(e.y), a);
                    if (r1 < lim2)
                        a = fmaf(__half2float(*(const __half*)(xs + r1)),
                                 __int_as_float(e.w), a);
                }
                acc[k] = a;
            }
            __syncthreads();
        }
#pragma unroll
        for (int k = 0; k < DPT; ++k)
            r_out[k] = fmaxf(acc[k] - dm[k], 0.f);
    }

    if (out == nullptr) {
#pragma unroll
        for (int k = 0; k < DPT; ++k) {
            int d = start + threadIdx.x + k * TPB;
            if (d < stop) xn[d] = __float2half_rn(r_out[k]);
        }
    } else {
        // LAST iteration: fused epilogue out[d,:] = g_w[d,:] * r (fp32 r)
        __syncthreads();                           // everyone done reading xs
        float* rs = (float*)xs;
#pragma unroll
        for (int k = 0; k < DPT; ++k) {
            int d = start + threadIdx.x + k * TPB;
            if (d < stop) rs[d - start] = r_out[k];
        }
        __syncthreads();
        const int rows = stop - start;
        if ((D & 3) == 0) {
            const int dq = D >> 2;
            const int total4 = rows * dq;
            const float4* w4 = (const float4*)(g_w + (size_t)start * D);
            float4*       o4 = (float4*)(out + (size_t)start * D);
            for (int i = threadIdx.x; i < total4; i += TPB) {
                float4 w = __ldg(w4 + i);
                float  r = rs[i / dq];
                o4[i] = make_float4(w.x * r, w.y * r, w.z * r, w.w * r);
            }
        } else {
            const int total = rows * D;
            for (int i = threadIdx.x; i < total; i += TPB)
                out[(size_t)start * D + i] = g_w[(size_t)start * D + i] * rs[i / D];
        }
    }
}

extern "C" void kernel_launch(void* const* d_in, const int* in_sizes, int n_in,
                              void* d_out, int out_size) {
    const float* fp  = (const float*)d_in[0];   // flow_proportions [B,N,D]
    const float* dem = (const float*)d_in[1];   // demands [B,N,1]
    const int*   adj = (const int*)d_in[2];     // adj_lst [B,N,D]
    const int*   ii  = (const int*)d_in[3];     // in_indices [B,N,D,3]
    const int*   nn  = (const int*)d_in[4];     // num_nodes scalar (device)

    const int E  = in_sizes[0];                 // B*N*D
    const int BN = in_sizes[1];                 // B*N
    const int D  = E / BN;

    void *pxa, *pxb, *pmc;
    cudaGetSymbolAddress(&pxa, g_xa);
    cudaGetSymbolAddress(&pxb, g_xb);
    cudaGetSymbolAddress(&pmc, g_maxcnt);
    __half* xa = (__half*)pxa;
    __half* xb = (__half*)pxb;

    int sm = 148;
    cudaDeviceGetAttribute(&sm, cudaDevAttrMultiProcessorCount, 0);
    const int grid = sm;                        // 152 on GB300 (divisible by B=4)

    cudaFuncSetAttribute(k_iter7, cudaFuncAttributeMaxDynamicSharedMemorySize,
                         SMEM_BYTES);

    const int BT = 256;
    const int gN = (BN + BT - 1) / BT;

    k_softmax<<<gN, BT>>>(fp, adj, nn, BN, D);
    cudaMemsetAsync(pmc, 0, sizeof(int), 0);
    k_gather<<<gN, BT>>>(ii, nn, BN, D);
    cudaMemsetAsync(xa, 0, (size_t)BN * sizeof(__half), 0);

    for (int i = 0; i < 32; ++i) {
        const __half* xo = (i & 1) ? xb : xa;
        __half*       xn = (i & 1) ? xa : xb;
        float* out = (i == 31) ? (float*)d_out : nullptr;
        k_iter7<<<grid, TPB, SMEM_BYTES>>>(dem, xo, xn, out, BN, D, nn);
    }
}

// round 8
// speedup vs baseline: 1.5386x; 1.0578x over previous
#include <cuda_runtime.h>
#include <cuda_fp16.h>
#include <cstdint>

// ---------------------------------------------------------------------------
// x_{k+1}[v] = relu( sum_d W[v,d]*x_k[src[v,d]] - demand[v] ), 32 iters,
// out = weights * x_32.  B=4, N=100K, D=16 (12 valid).
//
// R8: PERSISTENT kernel — all 32 iterations in one launch with a software
// grid barrier (1 block/SM guaranteed by 200KB smem => all blocks resident).
// Body per iteration = R7 (bulk-copy staging + uniform int4 pair walk +
// fused epilogue). Metadata loaded once. x reads bypass L1 (TMA / __ldcg).
// ---------------------------------------------------------------------------

#define MAXN       430000
#define MAXSLOT    16
#define MAXPAIR    (MAXSLOT / 2)
#define TPB        1024
#define DPT        4
#define SMEM_BYTES 200704      // dyn smem for staged fp16 x (N*2 <= this)
#define MAXIT      64

__device__ float g_w[(size_t)MAXN * MAXSLOT];    // softmax weights [dst][slot]
__device__ int4  g_e[(size_t)MAXPAIR * MAXN];    // edge pairs SoA [pair][dst]
__device__ int   g_maxcnt;                       // max valid edges per dst
__device__ unsigned g_ctr[MAXIT];                // per-iteration arrival counters
__device__ __align__(16) __half g_xa[MAXN];
__device__ __align__(16) __half g_xb[MAXN];

__device__ __forceinline__ unsigned smem_u32(const void* p) {
    unsigned r;
    asm("{ .reg .u64 t; cvta.to.shared.u64 t, %1; cvt.u32.u64 %0, t; }"
        : "=r"(r) : "l"(p));
    return r;
}

__device__ __forceinline__ void mbar_wait(unsigned mb, unsigned parity) {
    unsigned done;
    do {
        asm volatile("{ .reg .pred p; "
                     "mbarrier.try_wait.parity.acquire.cta.shared::cta.b64 p, [%1], %2, 0x989680; "
                     "selp.b32 %0, 1, 0, p; }"
                     : "=r"(done) : "r"(mb), "r"(parity) : "memory");
    } while (!done);
}

__device__ __forceinline__ unsigned ld_acq(const unsigned* p) {
    unsigned v;
    asm volatile("ld.acquire.gpu.u32 %0, [%1];" : "=r"(v) : "l"(p) : "memory");
    return v;
}

// --- K1: masked softmax over D slots (thread per node) ---------------------
__global__ void k_softmax(const float* __restrict__ fp, const int* __restrict__ adj,
                          const int* __restrict__ num_nodes, int BN, int D) {
    int t = blockIdx.x * blockDim.x + threadIdx.x;
    if (t >= BN) return;
    const int N = __ldg(num_nodes);
    const float* f = fp + (size_t)t * D;
    const int*   a = adj + (size_t)t * D;

    float m = -3.402823466e38f;
    for (int d = 0; d < D; ++d) {
        float v = __ldg(f + d);
        if (__ldg(a + d) == N) v -= 1e7f;
        m = fmaxf(m, v);
    }
    float s = 0.f;
    for (int d = 0; d < D; ++d) {
        float v = __ldg(f + d);
        if (__ldg(a + d) == N) v -= 1e7f;
        s += __expf(v - m);
    }
    float inv = 1.f / s;
    for (int d = 0; d < D; ++d) {
        float v = __ldg(f + d);
        if (__ldg(a + d) == N) v -= 1e7f;
        g_w[(size_t)t * D + d] = __expf(v - m) * inv;
    }
}

// --- K2: int4 row-pair edge records; valid edges first, zero-weight pads ---
__global__ void k_gather(const int* __restrict__ ii, const int* __restrict__ num_nodes,
                         int BN, int D) {
    int t = blockIdx.x * blockDim.x + threadIdx.x;
    if (t >= BN) return;
    const int N = __ldg(num_nodes);

    int off[MAXSLOT];
    int wb[MAXSLOT];
    int m = 0;
    for (int s = 0; s < D; ++s) {
        const int* r = ii + ((size_t)t * D + s) * 3;
        int fb = __ldg(r + 0);
        int fs = __ldg(r + 1);
        int fl = __ldg(r + 2);
        float w = g_w[((size_t)fb * N + fs) * D + fl];
        if (w != 0.0f) {
            off[m] = fs * 2;              // intra-batch smem byte offset
            wb[m]  = __float_as_int(w);
            ++m;
        }
    }
    for (int s = m; s < D; ++s) { off[s] = 0; wb[s] = 0; }

    const int P = D / 2;
    for (int p = 0; p < P; ++p)
        g_e[(size_t)p * BN + t] = make_int4(off[2 * p], wb[2 * p],
                                            off[2 * p + 1], wb[2 * p + 1]);
    atomicMax(&g_maxcnt, m);
}

// --- K3: persistent solver: all iterations + fused epilogue ----------------
__global__ void __launch_bounds__(TPB, 1) k_persist(const float* __restrict__ dem,
                                                    float* __restrict__ out,
                                                    int BN, int D, int niter,
                                                    const int* __restrict__ num_nodes) {
    extern __shared__ unsigned char xs[];
    __shared__ __align__(8) unsigned long long mbar;

    const int N    = __ldg(num_nodes);
    const int B    = BN / N;
    const int bpb  = gridDim.x / B;
    const int nblk = bpb * B;
    const int blk  = blockIdx.x;
    if (blk >= nblk) return;                       // never touches barrier
    const int b     = blk / bpb;
    const int ib    = blk - b * bpb;
    const int spb   = (N + bpb - 1) / bpb;
    const int start = b * N + ib * spb;
    const int stop  = min(start + spb, (b + 1) * N);
    const int P     = (g_maxcnt + 1) >> 1;

    const unsigned bytes = (unsigned)N * 2u;
    const bool whole   = (bytes <= SMEM_BYTES);
    const bool bulk_ok = whole && ((bytes & 15u) == 0u);

    const unsigned mb = smem_u32(&mbar);
    if (threadIdx.x == 0)
        asm volatile("mbarrier.init.shared.b64 [%0], %1;" :: "r"(mb), "r"(1) : "memory");

    // ---- iteration-invariant metadata, loaded ONCE --------------------------
    float dm[DPT];
    int   dl[DPT];
    int   kmax = 0;
#pragma unroll
    for (int k = 0; k < DPT; ++k) {
        int d = start + threadIdx.x + k * TPB;
        dl[k] = min(d, stop - 1);
        dm[k] = (d < stop) ? __ldg(dem + d) : 0.f;
        if (start + k * TPB < stop) kmax = k + 1;
    }
    __syncthreads();

    for (int it = 0; it < niter; ++it) {
        const __half* xo = (it & 1) ? g_xb : g_xa;
        __half*       xn = (it & 1) ? g_xa : g_xb;

        if (bulk_ok && threadIdx.x == 0) {
            asm volatile("mbarrier.arrive.expect_tx.shared.b64 _, [%0], %1;"
                         :: "r"(mb), "r"(bytes) : "memory");
            asm volatile("cp.async.bulk.shared::cta.global.mbarrier::complete_tx::bytes "
                         "[%0], [%1], %2, [%3];"
                         :: "r"(smem_u32(xs)), "l"(xo + (size_t)b * N), "r"(bytes), "r"(mb)
                         : "memory");
        }

        // prefetch first edge pair while the copy is in flight
        int4 e0[DPT];
#pragma unroll
        for (int k = 0; k < DPT; ++k) {
            if (k >= kmax) break;
            e0[k] = __ldg(&g_e[dl[k]]);
        }

        float r_out[DPT];
#pragma unroll
        for (int k = 0; k < DPT; ++k) r_out[k] = 0.f;

        if (whole) {
            if (!bulk_ok) {
                __half* dh = (__half*)xs;
                for (int i = threadIdx.x; i < N; i += TPB)
                    dh[i] = __ldcg(xo + (size_t)b * N + i);   // L2-only read
                __syncthreads();
            } else {
                mbar_wait(mb, (unsigned)(it & 1));
            }

#pragma unroll
            for (int k = 0; k < DPT; ++k) {
                if (k >= kmax) break;
                const int4* ep = g_e + dl[k];
                float a = 0.f;
                int4 e = e0[k];
#pragma unroll 5
                for (int p = 1; p < P; ++p) {
                    int4 f = __ldg(ep + p * BN);
                    a = fmaf(__half2float(*(const __half*)(xs + e.x)), __int_as_float(e.y), a);
                    a = fmaf(__half2float(*(const __half*)(xs + e.z)), __int_as_float(e.w), a);
                    e = f;
                }
                a = fmaf(__half2float(*(const __half*)(xs + e.x)), __int_as_float(e.y), a);
                a = fmaf(__half2float(*(const __half*)(xs + e.z)), __int_as_float(e.w), a);
                r_out[k] = fmaxf(a - dm[k], 0.f);
            }
        } else {
            // chunked fallback (N*2 > smem): range-predicated, L2-only reads
            const int hpc = SMEM_BYTES / 2;
            const int cb  = (N + hpc - 1) / hpc;
            float acc[DPT];
#pragma unroll
            for (int k = 0; k < DPT; ++k) acc[k] = 0.f;
            for (int j = 0; j < cb; ++j) {
                const int lo  = j * hpc;
                const int lim = min(hpc, N - lo);
                __half* dh = (__half*)xs;
                for (int i = threadIdx.x; i < lim; i += TPB)
                    dh[i] = __ldcg(xo + (size_t)b * N + lo + i);
                __syncthreads();
                const unsigned base2 = (unsigned)lo * 2u, lim2 = (unsigned)lim * 2u;
#pragma unroll
                for (int k = 0; k < DPT; ++k) {
                    if (k >= kmax) break;
                    const int4* ep = g_e + dl[k];
                    float a = acc[k];
                    for (int p = 0; p < P; ++p) {
                        int4 e = __ldg(ep + p * BN);
                        unsigned r0 = (unsigned)e.x - base2;
                        unsigned r1 = (unsigned)e.z - base2;
                        if (r0 < lim2)
                            a = fmaf(__half2float(*(const __half*)(xs + r0)),
                                     __int_as_float(e.y), a);
                        if (r1 < lim2)
                            a = fmaf(__half2float(*(const __half*)(xs + r1)),
                                     __int_as_float(e.w), a);
                    }
                    acc[k] = a;
                }
                __syncthreads();
            }
#pragma unroll
            for (int k = 0; k < DPT; ++k)
                r_out[k] = fmaxf(acc[k] - dm[k], 0.f);
        }

        if (it == niter - 1) {
            // ---- fused epilogue: out[d,:] = g_w[d,:] * r (fp32) --------------
            __syncthreads();                       // everyone done reading xs
            float* rs = (float*)xs;
#pragma unroll
            for (int k = 0; k < DPT; ++k) {
                int d = start + threadIdx.x + k * TPB;
                if (d < stop) rs[d - start] = r_out[k];
            }
            __syncthreads();
            const int rows = stop - start;
            if ((D & 3) == 0) {
                const int dq = D >> 2;
                const int total4 = rows * dq;
                const float4* w4 = (const float4*)(g_w + (size_t)start * D);
                float4*       o4 = (float4*)(out + (size_t)start * D);
                for (int i = threadIdx.x; i < total4; i += TPB) {
                    float4 w = __ldg(w4 + i);
                    float  r = rs[i / dq];
                    o4[i] = make_float4(w.x * r, w.y * r, w.z * r, w.w * r);
                }
            } else {
                const int total = rows * D;
                for (int i = threadIdx.x; i < total; i += TPB)
                    out[(size_t)start * D + i] = g_w[(size_t)start * D + i] * rs[i / D];
            }
            // last iteration: kernel exit is the sync
        } else {
            // write new x (fp16) for the next iteration
#pragma unroll
            for (int k = 0; k < DPT; ++k) {
                int d = start + threadIdx.x + k * TPB;
                if (d < stop) xn[d] = __float2half_rn(r_out[k]);
            }

            // ---- software grid barrier ---------------------------------------
            __threadfence();                       // STG visible gpu-wide
            __syncthreads();                       // whole block done
            if (threadIdx.x == 0) {
                asm volatile("fence.proxy.async;" ::: "memory");  // order vs TMA reads
                atomicAdd(&g_ctr[it], 1u);
                while (ld_acq(&g_ctr[it]) < (unsigned)nblk) { }
            }
            __syncthreads();                       // block released
        }
    }
}

extern "C" void kernel_launch(void* const* d_in, const int* in_sizes, int n_in,
                              void* d_out, int out_size) {
    const float* fp  = (const float*)d_in[0];   // flow_proportions [B,N,D]
    const float* dem = (const float*)d_in[1];   // demands [B,N,1]
    const int*   adj = (const int*)d_in[2];     // adj_lst [B,N,D]
    const int*   ii  = (const int*)d_in[3];     // in_indices [B,N,D,3]
    const int*   nn  = (const int*)d_in[4];     // num_nodes scalar (device)

    const int E  = in_sizes[0];                 // B*N*D
    const int BN = in_sizes[1];                 // B*N
    const int D  = E / BN;
    const int NITER = 32;

    void *pxa, *pmc, *pct;
    cudaGetSymbolAddress(&pxa, g_xa);
    cudaGetSymbolAddress(&pmc, g_maxcnt);
    cudaGetSymbolAddress(&pct, g_ctr);

    int sm = 148;
    cudaDeviceGetAttribute(&sm, cudaDevAttrMultiProcessorCount, 0);
    const int grid = sm;   // 1 block/SM (200KB smem) => all resident: barrier safe

    cudaFuncSetAttribute(k_persist, cudaFuncAttributeMaxDynamicSharedMemorySize,
                         SMEM_BYTES);

    const int BT = 256;
    const int gN = (BN + BT - 1) / BT;

    k_softmax<<<gN, BT>>>(fp, adj, nn, BN, D);
    cudaMemsetAsync(pmc, 0, sizeof(int), 0);
    k_gather<<<gN, BT>>>(ii, nn, BN, D);
    cudaMemsetAsync(pxa, 0, (size_t)BN * sizeof(__half), 0);   // x_0 = 0
    cudaMemsetAsync(pct, 0, sizeof(unsigned) * MAXIT, 0);      // barrier counters

    k_persist<<<grid, TPB, SMEM_BYTES>>>(dem, (float*)d_out, BN, D, NITER, nn);
}

// round 9
// speedup vs baseline: 2.2008x; 1.4304x over previous
#include <cuda_runtime.h>
#include <cuda_fp16.h>
#include <cstdint>

// ---------------------------------------------------------------------------
// x_{k+1}[v] = relu( sum_d W[v,d]*x_k[src[v,d]] - demand[v] ), 32 iters,
// out = weights * x_32.  B=4, N=100K, D=16 (12 valid).
//
// R9: ONE persistent kernel does everything.
//   Phase A (prep): single-pass softmax (exp ONCE -> 6.4M MUFU, was 12.8M),
//     and edges built by SCATTER via adj (in_indices never read): node u,
//     slot d writes (off(u), w[u,d]) into g_e[row d][adj[u,d]]. Permutation
//     per slot => conflict-free. g_e pre-zeroed => pads are zero-weight.
//   Phase B: iterations. x0=0 shortcut (x1 = relu(-demand), no gather),
//     then 31 iterations of bulk-copy staging + uniform int4 pair walk,
//     fused epilogue on the last one. Grid barrier between phases/iters
//     (1 block/SM via 200KB smem => all blocks resident => safe).
// ---------------------------------------------------------------------------

#define MAXN       430000
#define MAXSLOT    16
#define MAXPAIR    (MAXSLOT / 2)
#define TPB        1024
#define DPT        4
#define SMEM_BYTES 200704      // dyn smem for staged fp16 x (N*2 <= this)
#define MAXIT      64

__device__ float g_w[(size_t)MAXN * MAXSLOT];    // softmax weights [dst][slot]
__device__ int4  g_e[(size_t)MAXPAIR * MAXN];    // edge pairs SoA [pair][dst]
__device__ int   g_maxcnt;                       // max populated row + 1
__device__ unsigned g_ctr[MAXIT];                // barrier counters
__device__ __align__(16) __half g_xa[MAXN];
__device__ __align__(16) __half g_xb[MAXN];

__device__ __forceinline__ unsigned smem_u32(const void* p) {
    unsigned r;
    asm("{ .reg .u64 t; cvta.to.shared.u64 t, %1; cvt.u32.u64 %0, t; }"
        : "=r"(r) : "l"(p));
    return r;
}

__device__ __forceinline__ void mbar_wait(unsigned mb, unsigned parity) {
    unsigned done;
    do {
        asm volatile("{ .reg .pred p; "
                     "mbarrier.try_wait.parity.acquire.cta.shared::cta.b64 p, [%1], %2, 0x989680; "
                     "selp.b32 %0, 1, 0, p; }"
                     : "=r"(done) : "r"(mb), "r"(parity) : "memory");
    } while (!done);
}

__device__ __forceinline__ unsigned ld_acq(const unsigned* p) {
    unsigned v;
    asm volatile("ld.acquire.gpu.u32 %0, [%1];" : "=r"(v) : "l"(p) : "memory");
    return v;
}

// software grid barrier: all nblk co-resident blocks arrive, then release
__device__ __forceinline__ void grid_bar(int slot, unsigned nblk) {
    __threadfence();                               // STGs visible gpu-wide
    __syncthreads();
    if (threadIdx.x == 0) {
        asm volatile("fence.proxy.async;" ::: "memory");   // order vs TMA reads
        atomicAdd(&g_ctr[slot], 1u);
        while (ld_acq(&g_ctr[slot]) < nblk) { }
    }
    __syncthreads();
}

// --- the whole pipeline in one persistent kernel ----------------------------
__global__ void __launch_bounds__(TPB, 1) k_all(const float* __restrict__ fp,
                                                const int*   __restrict__ adj,
                                                const float* __restrict__ dem,
                                                float*       __restrict__ out,
                                                int BN, int D, int niter,
                                                const int* __restrict__ num_nodes) {
    extern __shared__ unsigned char xs[];
    __shared__ __align__(8) unsigned long long mbar;

    const int N    = __ldg(num_nodes);
    const int B    = BN / N;
    const int bpb  = gridDim.x / B;
    const unsigned nblk = (unsigned)(bpb * B);
    const int blk  = blockIdx.x;
    if (blk >= (int)nblk) return;                  // never touches any barrier
    const int b     = blk / bpb;
    const int ib    = blk - b * bpb;
    const int spb   = (N + bpb - 1) / bpb;
    const int start = b * N + ib * spb;
    const int stop  = min(start + spb, (b + 1) * N);

    const unsigned mb = smem_u32(&mbar);
    if (threadIdx.x == 0)
        asm volatile("mbarrier.init.shared.b64 [%0], %1;" :: "r"(mb), "r"(1) : "memory");

    // ======================= PHASE A: prep =================================
    // single-pass softmax (exp once, no max-shift) + scatter edges via adj
    {
        const int gstride = (int)nblk * TPB;
        int maxd = 0;
        int2* e2 = (int2*)g_e;

        for (int t = blk * TPB + threadIdx.x; t < BN; t += gstride) {
            const int bb   = t / N;
            const int base = bb * N;
            const int u2   = (t - base) * 2;       // intra-batch smem byte offset

            if (D == MAXSLOT) {
                float e[MAXSLOT];
                int   a[MAXSLOT];
                float sum = 0.f;
                const float4* f4 = (const float4*)(fp + (size_t)t * MAXSLOT);
                const int4*   a4 = (const int4*)(adj + (size_t)t * MAXSLOT);
#pragma unroll
                for (int g = 0; g < 4; ++g) {
                    float4 f = __ldg(f4 + g);
                    int4   av = __ldg(a4 + g);
                    a[4*g+0] = av.x; a[4*g+1] = av.y; a[4*g+2] = av.z; a[4*g+3] = av.w;
                    e[4*g+0] = (av.x == N) ? 0.f : __expf(f.x);
                    e[4*g+1] = (av.y == N) ? 0.f : __expf(f.y);
                    e[4*g+2] = (av.z == N) ? 0.f : __expf(f.z);
                    e[4*g+3] = (av.w == N) ? 0.f : __expf(f.w);
                    sum += e[4*g+0] + e[4*g+1] + e[4*g+2] + e[4*g+3];
                }
                const float inv = 1.f / sum;
                float4* w4 = (float4*)(g_w + (size_t)t * MAXSLOT);
#pragma unroll
                for (int g = 0; g < 4; ++g)
                    w4[g] = make_float4(e[4*g+0]*inv, e[4*g+1]*inv,
                                        e[4*g+2]*inv, e[4*g+3]*inv);
#pragma unroll
                for (int d = 0; d < MAXSLOT; ++d) {
                    if (a[d] != N) {
                        int v = base + a[d];
                        e2[(((size_t)(d >> 1) * BN + v) << 1) + (d & 1)] =
                            make_int2(u2, __float_as_int(e[d] * inv));
                        maxd = max(maxd, d + 1);
                    }
                }
            } else {
                // generic D (<= MAXSLOT): scalar single pass
                float e[MAXSLOT];
                int   a[MAXSLOT];
                float sum = 0.f;
                for (int d = 0; d < D; ++d) {
                    a[d] = __ldg(adj + (size_t)t * D + d);
                    float f = __ldg(fp + (size_t)t * D + d);
                    e[d] = (a[d] == N) ? 0.f : __expf(f);
                    sum += e[d];
                }
                const float inv = 1.f / sum;
                for (int d = 0; d < D; ++d) {
                    g_w[(size_t)t * D + d] = e[d] * inv;
                    if (a[d] != N) {
                        int v = base + a[d];
                        e2[(((size_t)(d >> 1) * BN + v) << 1) + (d & 1)] =
                            make_int2(u2, __float_as_int(e[d] * inv));
                        maxd = max(maxd, d + 1);
                    }
                }
            }
        }
        // warp-reduce maxd, one atomic per warp
        maxd = __reduce_max_sync(0xffffffffu, maxd);
        if ((threadIdx.x & 31) == 0 && maxd > 0) atomicMax(&g_maxcnt, maxd);
    }

    grid_bar(32, nblk);                            // prep done everywhere

    const int P = (*(volatile int*)&g_maxcnt + 1) >> 1;   // pairs to walk

    // per-thread iteration-invariant metadata
    float dm[DPT];
    int   dl[DPT];
    int   kmax = 0;
#pragma unroll
    for (int k = 0; k < DPT; ++k) {
        int d = start + threadIdx.x + k * TPB;
        dl[k] = min(d, stop - 1);
        dm[k] = (d < stop) ? __ldg(dem + d) : 0.f;
        if (start + k * TPB < stop) kmax = k + 1;
    }

    const unsigned bytes = (unsigned)N * 2u;
    const bool whole   = (bytes <= SMEM_BYTES);
    const bool bulk_ok = whole && ((bytes & 15u) == 0u);

    // ======================= PHASE B: iterations ============================
    for (int it = 0; it < niter; ++it) {
        float r_out[DPT];

        if (it == 0) {
            // x0 = 0 => x1 = relu(-demand); no gather needed
#pragma unroll
            for (int k = 0; k < DPT; ++k) r_out[k] = fmaxf(-dm[k], 0.f);
        } else {
            const __half* xo = (it & 1) ? g_xb : g_xa;

            if (bulk_ok && threadIdx.x == 0) {
                asm volatile("mbarrier.arrive.expect_tx.shared.b64 _, [%0], %1;"
                             :: "r"(mb), "r"(bytes) : "memory");
                asm volatile("cp.async.bulk.shared::cta.global.mbarrier::complete_tx::bytes "
                             "[%0], [%1], %2, [%3];"
                             :: "r"(smem_u32(xs)), "l"(xo + (size_t)b * N), "r"(bytes), "r"(mb)
                             : "memory");
            }

            // prefetch first edge pair while the copy is in flight
            int4 e0[DPT];
#pragma unroll
            for (int k = 0; k < DPT; ++k) {
                if (k >= kmax) break;
                e0[k] = __ldcg(&g_e[dl[k]]);
            }

#pragma unroll
            for (int k = 0; k < DPT; ++k) r_out[k] = 0.f;

            if (whole) {
                if (!bulk_ok) {
                    __half* dh = (__half*)xs;
                    for (int i = threadIdx.x; i < N; i += TPB)
                        dh[i] = __ldcg(xo + (size_t)b * N + i);
                    __syncthreads();
                } else {
                    mbar_wait(mb, (unsigned)((it + 1) & 1));   // it=1 -> parity 0
                }

#pragma unroll
                for (int k = 0; k < DPT; ++k) {
                    if (k >= kmax) break;
                    const int4* ep = g_e + dl[k];
                    float a = 0.f;
                    int4 e = e0[k];
#pragma unroll 5
                    for (int p = 1; p < P; ++p) {
                        int4 f = __ldcg(ep + p * BN);
                        a = fmaf(__half2float(*(const __half*)(xs + e.x)), __int_as_float(e.y), a);
                        a = fmaf(__half2float(*(const __half*)(xs + e.z)), __int_as_float(e.w), a);
                        e = f;
                    }
                    a = fmaf(__half2float(*(const __half*)(xs + e.x)), __int_as_float(e.y), a);
                    a = fmaf(__half2float(*(const __half*)(xs + e.z)), __int_as_float(e.w), a);
                    r_out[k] = fmaxf(a - dm[k], 0.f);
                }
            } else {
                // chunked fallback (N*2 > smem): range-predicated
                const int hpc = SMEM_BYTES / 2;
                const int cb  = (N + hpc - 1) / hpc;
                float acc[DPT];
#pragma unroll
                for (int k = 0; k < DPT; ++k) acc[k] = 0.f;
                for (int j = 0; j < cb; ++j) {
                    const int lo  = j * hpc;
                    const int lim = min(hpc, N - lo);
                    __half* dh = (__half*)xs;
                    for (int i = threadIdx.x; i < lim; i += TPB)
                        dh[i] = __ldcg(xo + (size_t)b * N + lo + i);
                    __syncthreads();
                    const unsigned base2 = (unsigned)lo * 2u, lim2 = (unsigned)lim * 2u;
#pragma unroll
                    for (int k = 0; k < DPT; ++k) {
                        if (k >= kmax) break;
                        const int4* ep = g_e + dl[k];
                        float a = acc[k];
                        for (int p = 0; p < P; ++p) {
                            int4 e = __ldcg(ep + p * BN);
                            unsigned r0 = (unsigned)e.x - base2;
                            unsigned r1 = (unsigned)e.z - base2;
                            if (r0 < lim2)
                                a = fmaf(__half2float(*(const __half*)(xs + r0)),
                                         __int_as_float(e.y), a);
                            if (r1 < lim2)
                                a = fmaf(__half2float(*(const __half*)(xs + r1)),
                                         __int_as_float(e.w), a);
                        }
                        acc[k] = a;
                    }
                    __syncthreads();
                }
#pragma unroll
                for (int k = 0; k < DPT; ++k)
                    r_out[k] = fmaxf(acc[k] - dm[k], 0.f);
            }
        }

        if (it == niter - 1) {
            // ---- fused epilogue: out[d,:] = g_w[d,:] * r (fp32) --------------
            __syncthreads();                       // everyone done reading xs
            float* rs = (float*)xs;
#pragma unroll
            for (int k = 0; k < DPT; ++k) {
                int d = start + threadIdx.x + k * TPB;
                if (d < stop) rs[d - start] = r_out[k];
            }
            __syncthreads();
            const int rows = stop - start;
            if ((D & 3) == 0) {
                const int dq = D >> 2;
                const int total4 = rows * dq;
                const float4* w4 = (const float4*)(g_w + (size_t)start * D);
                float4*       o4 = (float4*)(out + (size_t)start * D);
                for (int i = threadIdx.x; i < total4; i += TPB) {
                    float4 w = __ldcg(w4 + i);
                    float  r = rs[i / dq];
                    o4[i] = make_float4(w.x * r, w.y * r, w.z * r, w.w * r);
                }
            } else {
                const int total = rows * D;
                for (int i = threadIdx.x; i < total; i += TPB)
                    out[(size_t)start * D + i] = g_w[(size_t)start * D + i] * rs[i / D];
            }
        } else {
            // write next x (fp16), then grid barrier
            __half* xn = (it & 1) ? g_xa : g_xb;
#pragma unroll
            for (int k = 0; k < DPT; ++k) {
                int d = start + threadIdx.x + k * TPB;
                if (d < stop) xn[d] = __float2half_rn(r_out[k]);
            }
            grid_bar(it, nblk);
        }
    }
}

extern "C" void kernel_launch(void* const* d_in, const int* in_sizes, int n_in,
                              void* d_out, int out_size) {
    const float* fp  = (const float*)d_in[0];   // flow_proportions [B,N,D]
    const float* dem = (const float*)d_in[1];   // demands [B,N,1]
    const int*   adj = (const int*)d_in[2];     // adj_lst [B,N,D]
    // d_in[3] (in_indices) no longer needed: edges scattered via adj
    const int*   nn  = (const int*)d_in[4];     // num_nodes scalar (device)

    const int E  = in_sizes[0];                 // B*N*D
    const int BN = in_sizes[1];                 // B*N
    const int D  = E / BN;
    const int NITER = 32;

    void *pe, *pmc, *pct;
    cudaGetSymbolAddress(&pe, g_e);
    cudaGetSymbolAddress(&pmc, g_maxcnt);
    cudaGetSymbolAddress(&pct, g_ctr);

    int sm = 148;
    cudaDeviceGetAttribute(&sm, cudaDevAttrMultiProcessorCount, 0);
    const int grid = sm;   // 1 block/SM (200KB smem) => all resident: barrier safe

    cudaFuncSetAttribute(k_all, cudaFuncAttributeMaxDynamicSharedMemorySize,
                         SMEM_BYTES);

    // zero only the edge rows that can ever be walked: (D/2 pairs) * BN * 16B
    const size_t ebytes = (size_t)((D + 1) / 2) * BN * sizeof(int4);
    cudaMemsetAsync(pe, 0, ebytes, 0);
    cudaMemsetAsync(pmc, 0, sizeof(int), 0);
    cudaMemsetAsync(pct, 0, sizeof(unsigned) * MAXIT, 0);

    k_all<<<grid, TPB, SMEM_BYTES>>>(fp, adj, dem, (float*)d_out, BN, D, NITER, nn);
}

// round 10
// speedup vs baseline: 2.2519x; 1.0232x over previous
#include <cuda_runtime.h>
#include <cuda_fp16.h>
#include <cstdint>

// ---------------------------------------------------------------------------
// x_{k+1}[v] = relu( sum_d W[v,d]*x_k[src[v,d]] - demand[v] ), 32 iters,
// out = weights * x_32.  B=4, N=100K, D=16 (12 valid).
//
// R10: edges compressed to 4B: u32 = fs (17b) | wq15 (15b), wq = w*32767.
// Accumulate in quantized space, scale once per dst (exact fp32 weights kept
// for the epilogue). LTS floor/iter: (30.4+19.2)MB/6300 ~ 4.4us (was 6.1).
// Per-batch grid barriers on separate cache lines. Rest = R9 structure.
// ---------------------------------------------------------------------------

#define MAXN       430000
#define MAXSLOT    16
#define MAXQUAD    4            // ceil(MAXSLOT/4)
#define TPB        1024
#define DPT        4
#define SMEM_BYTES 200704       // dyn smem for staged fp16 x (N*2 <= this)
#define MAXIT      33           // 32 iter barriers + 1 prep barrier
#define MAXB       16

__device__ float g_w[(size_t)MAXN * MAXSLOT];     // exact softmax weights (epilogue)
// packed mode (N*2 <= SMEM): rows 0..3 hold uint4 quads of packed u32 edges.
// wide mode   (N*2 >  SMEM): rows 0..3 = fs u32 quads, rows 4..7 = w f32-bit quads.
__device__ uint4 g_eq[(size_t)2 * MAXQUAD * MAXN];
__device__ int   g_maxcnt;
__device__ unsigned g_ctr[MAXIT * MAXB * 32];     // 128B-strided counters
__device__ __align__(16) __half g_xa[MAXN];
__device__ __align__(16) __half g_xb[MAXN];

__device__ __forceinline__ unsigned smem_u32(const void* p) {
    unsigned r;
    asm("{ .reg .u64 t; cvta.to.shared.u64 t, %1; cvt.u32.u64 %0, t; }"
        : "=r"(r) : "l"(p));
    return r;
}

__device__ __forceinline__ void mbar_wait(unsigned mb, unsigned parity) {
    unsigned done;
    do {
        asm volatile("{ .reg .pred p; "
                     "mbarrier.try_wait.parity.acquire.cta.shared::cta.b64 p, [%1], %2, 0x989680; "
                     "selp.b32 %0, 1, 0, p; }"
                     : "=r"(done) : "r"(mb), "r"(parity) : "memory");
    } while (!done);
}

__device__ __forceinline__ unsigned ld_acq(const unsigned* p) {
    unsigned v;
    asm volatile("ld.acquire.gpu.u32 %0, [%1];" : "=r"(v) : "l"(p) : "memory");
    return v;
}

// software barrier over `expect` co-resident blocks sharing counter `ctr`
__device__ __forceinline__ void bar_sync(unsigned* ctr, unsigned expect) {
    __threadfence();
    __syncthreads();
    if (threadIdx.x == 0) {
        asm volatile("fence.proxy.async;" ::: "memory");
        atomicAdd(ctr, 1u);
        while (ld_acq(ctr) < expect) { }
    }
    __syncthreads();
}

// --- everything in one persistent kernel ------------------------------------
__global__ void __launch_bounds__(TPB, 1) k_all(const float* __restrict__ fp,
                                                const int*   __restrict__ adj,
                                                const float* __restrict__ dem,
                                                float*       __restrict__ out,
                                                int BN, int D, int niter,
                                                const int* __restrict__ num_nodes) {
    extern __shared__ unsigned char xs[];
    __shared__ __align__(8) unsigned long long mbar;

    const int N    = __ldg(num_nodes);
    const int B    = BN / N;
    const int bpb  = gridDim.x / B;
    const unsigned nblk = (unsigned)(bpb * B);
    const int blk  = blockIdx.x;
    if (blk >= (int)nblk) return;                  // never touches any barrier
    const int b     = blk / bpb;
    const int ib    = blk - b * bpb;
    const int spb   = (N + bpb - 1) / bpb;
    const int start = b * N + ib * spb;
    const int stop  = min(start + spb, (b + 1) * N);

    const unsigned bytes = (unsigned)N * 2u;
    const bool whole   = (bytes <= SMEM_BYTES);    // packed 4B edges iff whole
    const bool bulk_ok = whole && ((bytes & 15u) == 0u);

    // per-batch barrier group (fall back to one group if B > MAXB)
    const int grp = (B <= MAXB) ? b : 0;
    const unsigned expect = (B <= MAXB) ? (unsigned)bpb : nblk;

    const unsigned mb = smem_u32(&mbar);
    if (threadIdx.x == 0)
        asm volatile("mbarrier.init.shared.b64 [%0], %1;" :: "r"(mb), "r"(1) : "memory");

    // ======================= PHASE A: prep =================================
    {
        const int gstride = (int)nblk * TPB;
        int maxd = 0;
        unsigned* e1 = (unsigned*)g_eq;

        for (int t = blk * TPB + threadIdx.x; t < BN; t += gstride) {
            const int bb   = t / N;
            const int base = bb * N;
            const int u    = t - base;             // intra-batch source index

            float e[MAXSLOT];
            int   a[MAXSLOT];
            float sum = 0.f;
            if (D == MAXSLOT) {
                const float4* f4 = (const float4*)(fp + (size_t)t * MAXSLOT);
                const int4*   a4 = (const int4*)(adj + (size_t)t * MAXSLOT);
#pragma unroll
                for (int g = 0; g < 4; ++g) {
                    float4 f = __ldg(f4 + g);
                    int4   av = __ldg(a4 + g);
                    a[4*g+0] = av.x; a[4*g+1] = av.y; a[4*g+2] = av.z; a[4*g+3] = av.w;
                    e[4*g+0] = (av.x == N) ? 0.f : __expf(f.x);
                    e[4*g+1] = (av.y == N) ? 0.f : __expf(f.y);
                    e[4*g+2] = (av.z == N) ? 0.f : __expf(f.z);
                    e[4*g+3] = (av.w == N) ? 0.f : __expf(f.w);
                    sum += e[4*g+0] + e[4*g+1] + e[4*g+2] + e[4*g+3];
                }
            } else {
                for (int d = 0; d < D; ++d) {
                    a[d] = __ldg(adj + (size_t)t * D + d);
                    float f = __ldg(fp + (size_t)t * D + d);
                    e[d] = (a[d] == N) ? 0.f : __expf(f);
                    sum += e[d];
                }
            }
            const float inv = 1.f / sum;

            // exact fp32 weights for the epilogue
            if (D == MAXSLOT) {
                float4* w4 = (float4*)(g_w + (size_t)t * MAXSLOT);
#pragma unroll
                for (int g = 0; g < 4; ++g)
                    w4[g] = make_float4(e[4*g+0]*inv, e[4*g+1]*inv,
                                        e[4*g+2]*inv, e[4*g+3]*inv);
            } else {
                for (int d = 0; d < D; ++d)
                    g_w[(size_t)t * D + d] = e[d] * inv;
            }

            // scatter edges to destinations
            for (int d = 0; d < D; ++d) {
                if (a[d] != N) {
                    const int v = base + a[d];
                    const int q = d >> 2;
                    const float w = e[d] * inv;
                    const size_t lane = (((size_t)q * BN + v) << 2) + (d & 3);
                    if (whole) {
                        unsigned wq = (unsigned)(w * 32767.f + 0.5f);
                        if (wq > 32767u) wq = 32767u;
                        e1[lane] = (unsigned)u | (wq << 17);
                    } else {
                        e1[lane] = (unsigned)u;                       // fs
                        e1[(((size_t)(MAXQUAD + q) * BN + v) << 2) + (d & 3)] =
                            __float_as_uint(w);                       // w bits
                    }
                    maxd = max(maxd, d + 1);
                }
            }
        }
        maxd = __reduce_max_sync(0xffffffffu, maxd);
        if ((threadIdx.x & 31) == 0 && maxd > 0) atomicMax(&g_maxcnt, maxd);
    }

    // global prep barrier (prep writes cross batches)
    bar_sync(&g_ctr[(MAXIT - 1) * MAXB * 32], nblk);

    const int Q = (*(volatile int*)&g_maxcnt + 3) >> 2;   // quads per dst

    // iteration-invariant per-thread metadata
    float dm[DPT];
    int   dl[DPT];
    int   kmax = 0;
#pragma unroll
    for (int k = 0; k < DPT; ++k) {
        int d = start + threadIdx.x + k * TPB;
        dl[k] = min(d, stop - 1);
        dm[k] = (d < stop) ? __ldg(dem + d) : 0.f;
        if (start + k * TPB < stop) kmax = k + 1;
    }

    const __half* xh = (const __half*)xs;
    const float INV15 = 1.0f / 32767.0f;

    // ======================= PHASE B: iterations ============================
    for (int it = 0; it < niter; ++it) {
        float r_out[DPT];

        if (it == 0) {
            // x0 = 0 => x1 = relu(-demand)
#pragma unroll
            for (int k = 0; k < DPT; ++k) r_out[k] = fmaxf(-dm[k], 0.f);
        } else {
            const __half* xo = (it & 1) ? g_xb : g_xa;

            if (bulk_ok && threadIdx.x == 0) {
                asm volatile("mbarrier.arrive.expect_tx.shared.b64 _, [%0], %1;"
                             :: "r"(mb), "r"(bytes) : "memory");
                asm volatile("cp.async.bulk.shared::cta.global.mbarrier::complete_tx::bytes "
                             "[%0], [%1], %2, [%3];"
                             :: "r"(smem_u32(xs)), "l"(xo + (size_t)b * N), "r"(bytes), "r"(mb)
                             : "memory");
            }

            if (whole) {
                // prefetch quad 0 of each dst while the copy is in flight
                uint4 e0[DPT];
#pragma unroll
                for (int k = 0; k < DPT; ++k) {
                    if (k >= kmax) break;
                    e0[k] = __ldcg(&g_eq[dl[k]]);
                }

                if (!bulk_ok) {
                    __half* dh = (__half*)xs;
                    for (int i = threadIdx.x; i < N; i += TPB)
                        dh[i] = __ldcg(xo + (size_t)b * N + i);
                    __syncthreads();
                } else {
                    mbar_wait(mb, (unsigned)((it + 1) & 1));   // it=1 -> parity 0
                }

#pragma unroll
                for (int k = 0; k < DPT; ++k) {
                    if (k >= kmax) { r_out[k] = 0.f; continue; }
                    const uint4* ep = g_eq + dl[k];
                    float a = 0.f;
                    uint4 e = e0[k];
#pragma unroll 3
                    for (int q = 1; q < Q; ++q) {
                        uint4 f = __ldcg(ep + (size_t)q * BN);
                        a = fmaf(__uint2float_rn(e.x >> 17), __half2float(xh[e.x & 0x1FFFFu]), a);
                        a = fmaf(__uint2float_rn(e.y >> 17), __half2float(xh[e.y & 0x1FFFFu]), a);
                        a = fmaf(__uint2float_rn(e.z >> 17), __half2float(xh[e.z & 0x1FFFFu]), a);
                        a = fmaf(__uint2float_rn(e.w >> 17), __half2float(xh[e.w & 0x1FFFFu]), a);
                        e = f;
                    }
                    a = fmaf(__uint2float_rn(e.x >> 17), __half2float(xh[e.x & 0x1FFFFu]), a);
                    a = fmaf(__uint2float_rn(e.y >> 17), __half2float(xh[e.y & 0x1FFFFu]), a);
                    a = fmaf(__uint2float_rn(e.z >> 17), __half2float(xh[e.z & 0x1FFFFu]), a);
                    a = fmaf(__uint2float_rn(e.w >> 17), __half2float(xh[e.w & 0x1FFFFu]), a);
                    r_out[k] = fmaxf(fmaf(a, INV15, -dm[k]), 0.f);
                }
            } else {
                // giant-N fallback: direct global gather, fp32 weights (wide fmt)
                const __half* xob = xo + (size_t)b * N;
#pragma unroll
                for (int k = 0; k < DPT; ++k) {
                    if (k >= kmax) { r_out[k] = 0.f; continue; }
                    const uint4* ep = g_eq + dl[k];
                    float a = 0.f;
                    for (int q = 0; q < Q; ++q) {
                        uint4 fs = __ldcg(ep + (size_t)q * BN);
                        uint4 wb = __ldcg(ep + (size_t)(MAXQUAD + q) * BN);
                        a = fmaf(__uint_as_float(wb.x), __half2float(__ldcg(xob + fs.x)), a);
                        a = fmaf(__uint_as_float(wb.y), __half2float(__ldcg(xob + fs.y)), a);
                        a = fmaf(__uint_as_float(wb.z), __half2float(__ldcg(xob + fs.z)), a);
                        a = fmaf(__uint_as_float(wb.w), __half2float(__ldcg(xob + fs.w)), a);
                    }
                    r_out[k] = fmaxf(a - dm[k], 0.f);
                }
            }
        }

        if (it == niter - 1) {
            // ---- fused epilogue: out[d,:] = g_w[d,:] * r (exact fp32 w) ------
            __syncthreads();                       // everyone done reading xs
            float* rs = (float*)xs;
#pragma unroll
            for (int k = 0; k < DPT; ++k) {
                int d = start + threadIdx.x + k * TPB;
                if (d < stop) rs[d - start] = r_out[k];
            }
            __syncthreads();
            const int rows = stop - start;
            if ((D & 3) == 0) {
                const int dq = D >> 2;
                const int total4 = rows * dq;
                const float4* w4 = (const float4*)(g_w + (size_t)start * D);
                float4*       o4 = (float4*)(out + (size_t)start * D);
                for (int i = threadIdx.x; i < total4; i += TPB) {
                    float4 w = __ldcg(w4 + i);
                    float  r = rs[i / dq];
                    o4[i] = make_float4(w.x * r, w.y * r, w.z * r, w.w * r);
                }
            } else {
                const int total = rows * D;
                for (int i = threadIdx.x; i < total; i += TPB)
                    out[(size_t)start * D + i] = g_w[(size_t)start * D + i] * rs[i / D];
            }
        } else {
            // write next x (fp16), then per-batch barrier
            __half* xn = (it & 1) ? g_xa : g_xb;
#pragma unroll
            for (int k = 0; k < DPT; ++k) {
                int d = start + threadIdx.x + k * TPB;
                if (d < stop) xn[d] = __float2half_rn(r_out[k]);
            }
            bar_sync(&g_ctr[(it * MAXB + grp) * 32], expect);
        }
    }
}

extern "C" void kernel_launch(void* const* d_in, const int* in_sizes, int n_in,
                              void* d_out, int out_size) {
    const float* fp  = (const float*)d_in[0];   // flow_proportions [B,N,D]
    const float* dem = (const float*)d_in[1];   // demands [B,N,1]
    const int*   adj = (const int*)d_in[2];     // adj_lst [B,N,D]
    // d_in[3] (in_indices) not needed: edges scattered via adj
    const int*   nn  = (const int*)d_in[4];     // num_nodes scalar (device)

    const int E  = in_sizes[0];                 // B*N*D
    const int BN = in_sizes[1];                 // B*N
    const int D  = E / BN;
    const int NITER = 32;

    void *pe, *pmc, *pct;
    cudaGetSymbolAddress(&pe, g_eq);
    cudaGetSymbolAddress(&pmc, g_maxcnt);
    cudaGetSymbolAddress(&pct, g_ctr);

    int sm = 148;
    cudaDeviceGetAttribute(&sm, cudaDevAttrMultiProcessorCount, 0);
    const int grid = sm;    // 1 block/SM (200KB smem) => all resident: barriers safe

    cudaFuncSetAttribute(k_all, cudaFuncAttributeMaxDynamicSharedMemorySize,
                         SMEM_BYTES);

    // zero all edge rows that can be touched (packed rows + wide w rows)
    const size_t ebytes = (size_t)2 * MAXQUAD * BN * sizeof(uint4);
    cudaMemsetAsync(pe, 0, ebytes, 0);
    cudaMemsetAsync(pmc, 0, sizeof(int), 0);
    cudaMemsetAsync(pct, 0, sizeof(unsigned) * MAXIT * MAXB * 32, 0);

    k_all<<<grid, TPB, SMEM_BYTES>>>(fp, adj, dem, (float*)d_out, BN, D, NITER, nn);
}